// round 16
// baseline (speedup 1.0000x reference)
#include <cuda_runtime.h>
#include <cuda_bf16.h>
#include <cstdint>
#include <cstddef>

// GroupedLinearsAdvanced via mma.sync (HMMA, base sm_100 ISA) bf16 3-term split.
//   out[b,o,d] = sum_i x[b,i,d] * W[d,i,o] + bias[d,o]
// Kernel 1: x[b][i][d] -> x_t[d][b*128+i]  (fp32, coalesced both sides)
// Kernel 2: CTA = 4 d's. x -> B bf16 hi/lo [b][i]; W streamed in 4 chunks of
//   32 i, converted to A bf16 hi/lo [o][i]; per warp (d, o-half):
//   acc(f32) += Ah*Bh + Ah*Bl + Al*Bh via mma.sync.m16n8k16; epilogue adds
//   bias (pre-loaded into acc) and stores via smem transpose + float4 d-runs.
// (Resubmission: R15 bench was a container-infra failure, not a kernel result.)

#define IN_D   128
#define OUT_D  128
#define BSZ    16
#define D_TOT  4096
#define QTOT   2048
#define D_TILE 4
#define THREADS 256
#define CH     32            // i per chunk
#define NCH    4

__device__ float g_xt[(size_t)D_TOT * QTOT];   // x_t[d][b*128+i]

// ---- smem layout (bytes) ----
#define B_STRIDE 272                            // per B row (136 bf16)
#define B_SZB    (D_TILE * BSZ * B_STRIDE)      // 17408
#define B_HI_OFF 0
#define B_LO_OFF (B_HI_OFF + B_SZB)             // 17408
#define A_STRIDE 72                             // per A row (36 bf16, 32 used)
#define A_SZB    (D_TILE * OUT_D * A_STRIDE)    // 36864
#define A_HI_OFF (B_LO_OFF + B_SZB)             // 34816
#define A_LO_OFF (A_HI_OFF + A_SZB)             // 71680
#define STG_OFF  (A_LO_OFF + A_SZB)             // 108544
#define STG_D    (CH * 132 * 4)                 // 16896 per-d fp32 stage
#define SMEM_TOTAL (STG_OFF + D_TILE * STG_D)   // 176128

__device__ __forceinline__ void bf16split(float w, unsigned short& h, unsigned short& l) {
    __nv_bfloat16 hb = __float2bfloat16_rn(w);
    float hf = __bfloat162float(hb);
    __nv_bfloat16 lb = __float2bfloat16_rn(w - hf);
    h = *reinterpret_cast<unsigned short*>(&hb);
    l = *reinterpret_cast<unsigned short*>(&lb);
}
__device__ __forceinline__ void mma16816(float* c, const uint32_t a[4],
                                         uint32_t b0, uint32_t b1) {
    asm volatile(
        "mma.sync.aligned.m16n8k16.row.col.f32.bf16.bf16.f32 "
        "{%0,%1,%2,%3}, {%4,%5,%6,%7}, {%8,%9}, {%0,%1,%2,%3};"
        : "+f"(c[0]), "+f"(c[1]), "+f"(c[2]), "+f"(c[3])
        : "r"(a[0]), "r"(a[1]), "r"(a[2]), "r"(a[3]), "r"(b0), "r"(b1));
}

// ---------------------------------------------------------------------------
// Kernel 1: x[b][i][d] -> x_t[d][b*128+i]
// ---------------------------------------------------------------------------
__global__ void __launch_bounds__(256)
transpose_x_kernel(const float* __restrict__ x)
{
    __shared__ float tile[32][33];
    const int p0 = blockIdx.x * 32;     // fixed b, 32 consecutive i
    const int b  = p0 >> 7;
    const int i0 = p0 & 127;
    const int D  = blockIdx.y * 32;
    const int r    = threadIdx.x >> 5;
    const int lane = threadIdx.x & 31;

#pragma unroll
    for (int ii = r; ii < 32; ii += 8)
        tile[ii][lane] = x[((size_t)(b * IN_D) + i0 + ii) * D_TOT + D + lane];
    __syncthreads();
#pragma unroll
    for (int dd = r; dd < 32; dd += 8)
        g_xt[(size_t)(D + dd) * QTOT + p0 + lane] = tile[lane][dd];
}

// ---------------------------------------------------------------------------
// Kernel 2: mma.sync GEMM, 4 d-channels per CTA
// ---------------------------------------------------------------------------
__global__ void __launch_bounds__(THREADS, 1)
gemm_mma_kernel(const float* __restrict__ W,
                const float* __restrict__ bias,
                float* __restrict__ out)
{
    extern __shared__ __align__(16) char smem[];
    const int tid  = threadIdx.x;
    const int warp = tid >> 5;
    const int lane = tid & 31;
    const int dloc = warp >> 1;          // d within tile
    const int o0   = (warp & 1) * 64;    // o-half
    const int d0   = blockIdx.x * D_TILE;
    const int d    = d0 + dloc;

    // ---- accumulators pre-loaded with bias ----
    // c[mt][n][0..3]: D rows o = o0+mt*16+(lane>>2) (+8 for c2,c3),
    //                 cols b = n*8 + 2*(lane&3) (+1 for c1,c3)
    float c[4][2][4];
#pragma unroll
    for (int mt = 0; mt < 4; ++mt) {
        float b0v = bias[(size_t)d * OUT_D + o0 + mt * 16 + (lane >> 2)];
        float b8v = bias[(size_t)d * OUT_D + o0 + mt * 16 + (lane >> 2) + 8];
#pragma unroll
        for (int n = 0; n < 2; ++n) {
            c[mt][n][0] = b0v; c[mt][n][1] = b0v;
            c[mt][n][2] = b8v; c[mt][n][3] = b8v;
        }
    }

    // ---- B conversion: x_t (fp32 [b][i]) -> Bh/Bl bf16 rows [dl*16+b] ----
#pragma unroll
    for (int r = 0; r < 8; ++r) {
        int idx4 = tid + r * THREADS;            // 0..2047 float4s over 4 d
        int dl = idx4 >> 9;
        int rem = idx4 & 511;
        int q0 = rem * 4;
        int b  = q0 >> 7;
        int i  = q0 & 127;
        float4 v = *reinterpret_cast<const float4*>(
            g_xt + (size_t)(d0 + dl) * QTOT + q0);
        unsigned short h[4], l[4];
        bf16split(v.x, h[0], l[0]); bf16split(v.y, h[1], l[1]);
        bf16split(v.z, h[2], l[2]); bf16split(v.w, h[3], l[3]);
        uint2 hp = make_uint2((uint32_t)h[0] | ((uint32_t)h[1] << 16),
                              (uint32_t)h[2] | ((uint32_t)h[3] << 16));
        uint2 lp = make_uint2((uint32_t)l[0] | ((uint32_t)l[1] << 16),
                              (uint32_t)l[2] | ((uint32_t)l[3] << 16));
        uint32_t byteoff = (uint32_t)((dl * BSZ + b) * B_STRIDE + i * 2);
        *reinterpret_cast<uint2*>(smem + B_HI_OFF + byteoff) = hp;
        *reinterpret_cast<uint2*>(smem + B_LO_OFF + byteoff) = lp;
    }
    __syncthreads();

    // ---- chunk loop over K ----
    const int o   = tid & 127;       // convert role: output row
    const int ihf = tid >> 7;        // convert role: i-half (0: i 0-15, 1: 16-31)

#pragma unroll 1
    for (int c4 = 0; c4 < NCH; ++c4) {
        const int i0 = c4 * CH;

        // load W chunk (4 d x 32 i x 128 o fp32) into padded stages, coalesced
#pragma unroll
        for (int r = 0; r < 16; ++r) {
            int idx = tid + r * THREADS;     // 0..4095 float4s
            int dl = idx >> 10;
            int rem = idx & 1023;
            int ii = rem >> 5;
            int o4 = rem & 31;
            float4 v = *reinterpret_cast<const float4*>(
                W + (size_t)(d0 + dl) * IN_D * OUT_D + (size_t)(i0 + ii) * OUT_D + o4 * 4);
            *reinterpret_cast<float4*>(
                smem + STG_OFF + dl * STG_D + (ii * 132 + o4 * 4) * 4) = v;
        }
        __syncthreads();

        // convert: thread (o, ihf) transposes+splits 16 i's for each d
#pragma unroll
        for (int dl = 0; dl < D_TILE; ++dl) {
            const float* st = reinterpret_cast<const float*>(smem + STG_OFF + dl * STG_D);
            uint32_t ph[8], pl[8];
#pragma unroll
            for (int j2 = 0; j2 < 8; ++j2) {
                unsigned short h0, l0, h1, l1;
                bf16split(st[(ihf * 16 + 2 * j2)     * 132 + o], h0, l0);
                bf16split(st[(ihf * 16 + 2 * j2 + 1) * 132 + o], h1, l1);
                ph[j2] = (uint32_t)h0 | ((uint32_t)h1 << 16);
                pl[j2] = (uint32_t)l0 | ((uint32_t)l1 << 16);
            }
            uint32_t rowb = (uint32_t)((dl * OUT_D + o) * A_STRIDE + ihf * 32);
#pragma unroll
            for (int j8 = 0; j8 < 4; ++j8) {
                *reinterpret_cast<uint2*>(smem + A_HI_OFF + rowb + j8 * 8) =
                    make_uint2(ph[2 * j8], ph[2 * j8 + 1]);
                *reinterpret_cast<uint2*>(smem + A_LO_OFF + rowb + j8 * 8) =
                    make_uint2(pl[2 * j8], pl[2 * j8 + 1]);
            }
        }
        __syncthreads();

        // mma: 2 k16 steps per chunk
#pragma unroll
        for (int s = 0; s < 2; ++s) {
            // B fragments: row = dloc*16 + n*8 + lane>>2; col k = i0+s*16+(lane&3)*2
            uint32_t bh[2][2], bl[2][2];
#pragma unroll
            for (int n = 0; n < 2; ++n) {
                uint32_t rb = (uint32_t)((dloc * BSZ + n * 8 + (lane >> 2)) * B_STRIDE
                                         + (i0 + s * 16 + (lane & 3) * 2) * 2);
                bh[n][0] = *reinterpret_cast<const uint32_t*>(smem + B_HI_OFF + rb);
                bh[n][1] = *reinterpret_cast<const uint32_t*>(smem + B_HI_OFF + rb + 16);
                bl[n][0] = *reinterpret_cast<const uint32_t*>(smem + B_LO_OFF + rb);
                bl[n][1] = *reinterpret_cast<const uint32_t*>(smem + B_LO_OFF + rb + 16);
            }
#pragma unroll
            for (int mt = 0; mt < 4; ++mt) {
                uint32_t r0 = (uint32_t)((dloc * OUT_D + o0 + mt * 16 + (lane >> 2)) * A_STRIDE
                                         + (s * 16 + (lane & 3) * 2) * 2);
                uint32_t r8 = r0 + 8 * A_STRIDE;
                uint32_t ah[4], al[4];
                ah[0] = *reinterpret_cast<const uint32_t*>(smem + A_HI_OFF + r0);
                ah[1] = *reinterpret_cast<const uint32_t*>(smem + A_HI_OFF + r8);
                ah[2] = *reinterpret_cast<const uint32_t*>(smem + A_HI_OFF + r0 + 16);
                ah[3] = *reinterpret_cast<const uint32_t*>(smem + A_HI_OFF + r8 + 16);
                al[0] = *reinterpret_cast<const uint32_t*>(smem + A_LO_OFF + r0);
                al[1] = *reinterpret_cast<const uint32_t*>(smem + A_LO_OFF + r8);
                al[2] = *reinterpret_cast<const uint32_t*>(smem + A_LO_OFF + r0 + 16);
                al[3] = *reinterpret_cast<const uint32_t*>(smem + A_LO_OFF + r8 + 16);
#pragma unroll
                for (int n = 0; n < 2; ++n) {
                    mma16816(c[mt][n], ah, bh[n][0], bh[n][1]);
                    mma16816(c[mt][n], ah, bl[n][0], bl[n][1]);
                    mma16816(c[mt][n], al, bh[n][0], bh[n][1]);
                }
            }
        }
        __syncthreads();   // before next chunk overwrites stage/A
    }

    // ---- epilogue: write D tiles into smem (reuse A region), then store ----
    float* outs = reinterpret_cast<float*>(smem + A_HI_OFF);   // [dl][b*128+o]
#pragma unroll
    for (int mt = 0; mt < 4; ++mt) {
#pragma unroll
        for (int n = 0; n < 2; ++n) {
            int oo = o0 + mt * 16 + (lane >> 2);
            int bb = n * 8 + 2 * (lane & 3);
            outs[dloc * 2048 + bb       * 128 + oo    ] = c[mt][n][0];
            outs[dloc * 2048 + (bb + 1) * 128 + oo    ] = c[mt][n][1];
            outs[dloc * 2048 + bb       * 128 + oo + 8] = c[mt][n][2];
            outs[dloc * 2048 + (bb + 1) * 128 + oo + 8] = c[mt][n][3];
        }
    }
    __syncthreads();

    // coalesced store: each (b,o) pair p gets a 4-float d-run (one float4;
    // adjacent-d0 CTAs fill the sector's other half, merged in L2)
#pragma unroll
    for (int r = 0; r < 2; ++r) {
        int p4 = 4 * (tid + r * THREADS);
        float v[D_TILE][4];
#pragma unroll
        for (int cc = 0; cc < D_TILE; ++cc) {
            float4 t4 = *reinterpret_cast<float4*>(&outs[cc * 2048 + p4]);
            v[cc][0] = t4.x; v[cc][1] = t4.y; v[cc][2] = t4.z; v[cc][3] = t4.w;
        }
#pragma unroll
        for (int pp = 0; pp < 4; ++pp) {
            int p = p4 + pp;                  // p = b*128 + o
            float* op = out + (size_t)p * D_TOT + d0;
            *reinterpret_cast<float4*>(op) =
                make_float4(v[0][pp], v[1][pp], v[2][pp], v[3][pp]);
        }
    }
}

extern "C" void kernel_launch(void* const* d_in, const int* in_sizes, int n_in,
                              void* d_out, int out_size)
{
    (void)in_sizes; (void)n_in; (void)out_size;
    const float* x    = (const float*)d_in[0];
    const float* W    = (const float*)d_in[1];
    const float* bias = (const float*)d_in[2];
    float*       out  = (float*)d_out;

    cudaFuncSetAttribute(gemm_mma_kernel,
                         cudaFuncAttributeMaxDynamicSharedMemorySize, SMEM_TOTAL);

    dim3 tgrid(QTOT / 32, D_TOT / 32);   // (64, 128)
    transpose_x_kernel<<<tgrid, 256>>>(x);
    gemm_mma_kernel<<<D_TOT / D_TILE, THREADS, SMEM_TOTAL>>>(W, bias, out);
}

// round 17
// speedup vs baseline: 1.3287x; 1.3287x over previous
#include <cuda_runtime.h>
#include <cuda_bf16.h>
#include <cstdint>
#include <cstddef>

// GroupedLinearsAdvanced via mma.sync bf16 3-term split, pipelined.
//   out[b,o,d] = sum_i x[b,i,d] * W[d,i,o] + bias[d,o]
// R16: D_TILE=2, CH=16, 128 thr, cp.async double-buffered W stage ->
// 71.7KB smem -> 3 CTAs/SM; W chunk c+1 streams while chunk c converts
// and mmas. Math identical to the verified R14 kernel (rel_err 4.5e-6).

#define IN_D   128
#define OUT_D  128
#define BSZ    16
#define D_TOT  4096
#define QTOT   2048
#define D_TILE 2
#define THREADS 128
#define CH     16            // i per chunk = one k16 step
#define NCH    8

__device__ float g_xt[(size_t)D_TOT * QTOT];   // x_t[d][b*128+i]

// ---- smem layout (bytes) ----
#define B_STRIDE 272                            // per B row (136 bf16)
#define B_SZB    (D_TILE * BSZ * B_STRIDE)      // 8704
#define B_HI_OFF 0
#define B_LO_OFF (B_HI_OFF + B_SZB)             // 8704
#define A_STRIDE 40                             // per A row (16 i = 32B + 8 pad)
#define A_SZB    (D_TILE * OUT_D * A_STRIDE)    // 10240
#define A_HI_OFF (B_LO_OFF + B_SZB)             // 17408
#define A_LO_OFF (A_HI_OFF + A_SZB)             // 27648
#define STG_OFF  (A_LO_OFF + A_SZB)             // 37888 (16B aligned)
#define STG_D    (CH * 132 * 4)                 // 8448 per-d fp32 stage
#define STG_BUF  (D_TILE * STG_D)               // 16896 per buffer
#define SMEM_TOTAL (STG_OFF + 2 * STG_BUF)      // 71680

__device__ __forceinline__ void bf16split(float w, unsigned short& h, unsigned short& l) {
    __nv_bfloat16 hb = __float2bfloat16_rn(w);
    float hf = __bfloat162float(hb);
    __nv_bfloat16 lb = __float2bfloat16_rn(w - hf);
    h = *reinterpret_cast<unsigned short*>(&hb);
    l = *reinterpret_cast<unsigned short*>(&lb);
}
__device__ __forceinline__ void mma16816(float* c, const uint32_t a[4],
                                         uint32_t b0, uint32_t b1) {
    asm volatile(
        "mma.sync.aligned.m16n8k16.row.col.f32.bf16.bf16.f32 "
        "{%0,%1,%2,%3}, {%4,%5,%6,%7}, {%8,%9}, {%0,%1,%2,%3};"
        : "+f"(c[0]), "+f"(c[1]), "+f"(c[2]), "+f"(c[3])
        : "r"(a[0]), "r"(a[1]), "r"(a[2]), "r"(a[3]), "r"(b0), "r"(b1));
}
__device__ __forceinline__ void cp_async16(uint32_t dst, const void* src) {
    asm volatile("cp.async.cg.shared.global [%0], [%1], 16;"
                 :: "r"(dst), "l"(src) : "memory");
}
__device__ __forceinline__ void cp_commit() {
    asm volatile("cp.async.commit_group;" ::: "memory");
}
__device__ __forceinline__ void cp_wait1() {
    asm volatile("cp.async.wait_group 1;" ::: "memory");
}
__device__ __forceinline__ void cp_wait0() {
    asm volatile("cp.async.wait_group 0;" ::: "memory");
}

// ---------------------------------------------------------------------------
// Kernel 1: x[b][i][d] -> x_t[d][b*128+i]
// ---------------------------------------------------------------------------
__global__ void __launch_bounds__(256)
transpose_x_kernel(const float* __restrict__ x)
{
    __shared__ float tile[32][33];
    const int p0 = blockIdx.x * 32;     // fixed b, 32 consecutive i
    const int b  = p0 >> 7;
    const int i0 = p0 & 127;
    const int D  = blockIdx.y * 32;
    const int r    = threadIdx.x >> 5;
    const int lane = threadIdx.x & 31;

#pragma unroll
    for (int ii = r; ii < 32; ii += 8)
        tile[ii][lane] = x[((size_t)(b * IN_D) + i0 + ii) * D_TOT + D + lane];
    __syncthreads();
#pragma unroll
    for (int dd = r; dd < 32; dd += 8)
        g_xt[(size_t)(D + dd) * QTOT + p0 + lane] = tile[lane][dd];
}

// ---------------------------------------------------------------------------
// Kernel 2: pipelined mma.sync GEMM, 2 d-channels per CTA
// ---------------------------------------------------------------------------
__global__ void __launch_bounds__(THREADS, 3)
gemm_mma_kernel(const float* __restrict__ W,
                const float* __restrict__ bias,
                float* __restrict__ out)
{
    extern __shared__ __align__(16) char smem[];
    const int tid  = threadIdx.x;
    const int warp = tid >> 5;           // 0..3
    const int lane = tid & 31;
    const int dloc = warp >> 1;          // d within tile: 0..1
    const int o0   = (warp & 1) * 64;    // o-half
    const int d0   = blockIdx.x * D_TILE;
    const int d    = d0 + dloc;
    const uint32_t sb = (uint32_t)__cvta_generic_to_shared(smem);

    // ---- cp.async issue helper data ----
    // per chunk: 2 dl x 16 ii x 32 o4 = 1024 cp16 ops, 8 per thread
    const int cdl = tid >> 6;                 // reuse pattern below per r

    // ---- prologue: stream chunk 0 into buffer 0 ----
#pragma unroll
    for (int r = 0; r < 8; ++r) {
        int idx = tid + r * THREADS;          // 0..1023
        int dl  = idx >> 9;
        int rem = idx & 511;
        int ii  = rem >> 5;
        int o4  = rem & 31;
        cp_async16(sb + STG_OFF + dl * STG_D + (uint32_t)(ii * 528 + o4 * 16),
                   W + (size_t)(d0 + dl) * IN_D * OUT_D + (size_t)ii * OUT_D + o4 * 4);
    }
    cp_commit();
    (void)cdl;

    // ---- accumulators pre-loaded with bias ----
    float c[4][2][4];
#pragma unroll
    for (int mt = 0; mt < 4; ++mt) {
        float b0v = bias[(size_t)d * OUT_D + o0 + mt * 16 + (lane >> 2)];
        float b8v = bias[(size_t)d * OUT_D + o0 + mt * 16 + (lane >> 2) + 8];
#pragma unroll
        for (int n = 0; n < 2; ++n) {
            c[mt][n][0] = b0v; c[mt][n][1] = b0v;
            c[mt][n][2] = b8v; c[mt][n][3] = b8v;
        }
    }

    // ---- B conversion: x_t (fp32 [b][i]) -> Bh/Bl bf16 rows [dl*16+b] ----
#pragma unroll
    for (int r = 0; r < 8; ++r) {
        int idx4 = tid + r * THREADS;         // 0..1023 float4s over 2 d
        int dl = idx4 >> 9;
        int rem = idx4 & 511;
        int q0 = rem * 4;
        int b  = q0 >> 7;
        int i  = q0 & 127;
        float4 v = *reinterpret_cast<const float4*>(
            g_xt + (size_t)(d0 + dl) * QTOT + q0);
        unsigned short h[4], l[4];
        bf16split(v.x, h[0], l[0]); bf16split(v.y, h[1], l[1]);
        bf16split(v.z, h[2], l[2]); bf16split(v.w, h[3], l[3]);
        uint2 hp = make_uint2((uint32_t)h[0] | ((uint32_t)h[1] << 16),
                              (uint32_t)h[2] | ((uint32_t)h[3] << 16));
        uint2 lp = make_uint2((uint32_t)l[0] | ((uint32_t)l[1] << 16),
                              (uint32_t)l[2] | ((uint32_t)l[3] << 16));
        uint32_t byteoff = (uint32_t)((dl * BSZ + b) * B_STRIDE + i * 2);
        *reinterpret_cast<uint2*>(smem + B_HI_OFF + byteoff) = hp;
        *reinterpret_cast<uint2*>(smem + B_LO_OFF + byteoff) = lp;
    }

    // ---- chunk loop: convert+mma chunk c while chunk c+1 streams ----
    const int o = tid;                        // convert role: one A row per thread

#pragma unroll 1
    for (int c4 = 0; c4 < NCH; ++c4) {
        if (c4 + 1 < NCH) {
            const int i0n = (c4 + 1) * CH;
            const uint32_t bufn = (uint32_t)(((c4 + 1) & 1) * STG_BUF);
#pragma unroll
            for (int r = 0; r < 8; ++r) {
                int idx = tid + r * THREADS;
                int dl  = idx >> 9;
                int rem = idx & 511;
                int ii  = rem >> 5;
                int o4  = rem & 31;
                cp_async16(sb + STG_OFF + bufn + dl * STG_D + (uint32_t)(ii * 528 + o4 * 16),
                           W + (size_t)(d0 + dl) * IN_D * OUT_D
                             + (size_t)(i0n + ii) * OUT_D + o4 * 4);
            }
            cp_commit();
            cp_wait1();
        } else {
            cp_wait0();
        }
        __syncthreads();                      // chunk c4 resident for all threads

        // convert: thread o transposes+splits 16 i for each dl
        const uint32_t buf = (uint32_t)((c4 & 1) * STG_BUF);
#pragma unroll
        for (int dl = 0; dl < D_TILE; ++dl) {
            const float* st = reinterpret_cast<const float*>(smem + STG_OFF + buf + dl * STG_D);
            uint32_t ph[8], pl[8];
#pragma unroll
            for (int j2 = 0; j2 < 8; ++j2) {
                unsigned short h0, l0, h1, l1;
                bf16split(st[(2 * j2)     * 132 + o], h0, l0);
                bf16split(st[(2 * j2 + 1) * 132 + o], h1, l1);
                ph[j2] = (uint32_t)h0 | ((uint32_t)h1 << 16);
                pl[j2] = (uint32_t)l0 | ((uint32_t)l1 << 16);
            }
            uint32_t rowb = (uint32_t)((dl * OUT_D + o) * A_STRIDE);
#pragma unroll
            for (int j8 = 0; j8 < 4; ++j8) {
                *reinterpret_cast<uint2*>(smem + A_HI_OFF + rowb + j8 * 8) =
                    make_uint2(ph[2 * j8], ph[2 * j8 + 1]);
                *reinterpret_cast<uint2*>(smem + A_LO_OFF + rowb + j8 * 8) =
                    make_uint2(pl[2 * j8], pl[2 * j8 + 1]);
            }
        }
        __syncthreads();

        // mma: one k16 step (k base = c4*16 for B, 0 for A rows)
        {
            uint32_t bh[2][2], bl[2][2];
#pragma unroll
            for (int n = 0; n < 2; ++n) {
                uint32_t rb = (uint32_t)((dloc * BSZ + n * 8 + (lane >> 2)) * B_STRIDE
                                         + (c4 * 16 + (lane & 3) * 2) * 2);
                bh[n][0] = *reinterpret_cast<const uint32_t*>(smem + B_HI_OFF + rb);
                bh[n][1] = *reinterpret_cast<const uint32_t*>(smem + B_HI_OFF + rb + 16);
                bl[n][0] = *reinterpret_cast<const uint32_t*>(smem + B_LO_OFF + rb);
                bl[n][1] = *reinterpret_cast<const uint32_t*>(smem + B_LO_OFF + rb + 16);
            }
#pragma unroll
            for (int mt = 0; mt < 4; ++mt) {
                uint32_t r0 = (uint32_t)((dloc * OUT_D + o0 + mt * 16 + (lane >> 2)) * A_STRIDE
                                         + (lane & 3) * 4);
                uint32_t r8 = r0 + 8 * A_STRIDE;
                uint32_t ah[4], al[4];
                ah[0] = *reinterpret_cast<const uint32_t*>(smem + A_HI_OFF + r0);
                ah[1] = *reinterpret_cast<const uint32_t*>(smem + A_HI_OFF + r8);
                ah[2] = *reinterpret_cast<const uint32_t*>(smem + A_HI_OFF + r0 + 16);
                ah[3] = *reinterpret_cast<const uint32_t*>(smem + A_HI_OFF + r8 + 16);
                al[0] = *reinterpret_cast<const uint32_t*>(smem + A_LO_OFF + r0);
                al[1] = *reinterpret_cast<const uint32_t*>(smem + A_LO_OFF + r8);
                al[2] = *reinterpret_cast<const uint32_t*>(smem + A_LO_OFF + r0 + 16);
                al[3] = *reinterpret_cast<const uint32_t*>(smem + A_LO_OFF + r8 + 16);
#pragma unroll
                for (int n = 0; n < 2; ++n) {
                    mma16816(c[mt][n], ah, bh[n][0], bh[n][1]);
                    mma16816(c[mt][n], ah, bl[n][0], bl[n][1]);
                    mma16816(c[mt][n], al, bh[n][0], bh[n][1]);
                }
            }
        }
        __syncthreads();                      // before next convert overwrites A
    }

    // ---- epilogue: D tiles -> smem (reuse B region), then float2 d-runs ----
    float* outs = reinterpret_cast<float*>(smem);     // [dl][b*128+o], 16KB
#pragma unroll
    for (int mt = 0; mt < 4; ++mt) {
#pragma unroll
        for (int n = 0; n < 2; ++n) {
            int oo = o0 + mt * 16 + (lane >> 2);
            int bb = n * 8 + 2 * (lane & 3);
            outs[dloc * 2048 + bb       * 128 + oo    ] = c[mt][n][0];
            outs[dloc * 2048 + (bb + 1) * 128 + oo    ] = c[mt][n][1];
            outs[dloc * 2048 + bb       * 128 + oo + 8] = c[mt][n][2];
            outs[dloc * 2048 + (bb + 1) * 128 + oo + 8] = c[mt][n][3];
        }
    }
    __syncthreads();

#pragma unroll
    for (int r = 0; r < 16; ++r) {
        int p = tid + r * THREADS;            // p = b*128 + o
        float2 v = make_float2(outs[p], outs[2048 + p]);
        *reinterpret_cast<float2*>(out + (size_t)p * D_TOT + d0) = v;
    }
}

extern "C" void kernel_launch(void* const* d_in, const int* in_sizes, int n_in,
                              void* d_out, int out_size)
{
    (void)in_sizes; (void)n_in; (void)out_size;
    const float* x    = (const float*)d_in[0];
    const float* W    = (const float*)d_in[1];
    const float* bias = (const float*)d_in[2];
    float*       out  = (float*)d_out;

    cudaFuncSetAttribute(gemm_mma_kernel,
                         cudaFuncAttributeMaxDynamicSharedMemorySize, SMEM_TOTAL);

    dim3 tgrid(QTOT / 32, D_TOT / 32);   // (64, 128)
    transpose_x_kernel<<<tgrid, 256>>>(x);
    gemm_mma_kernel<<<D_TOT / D_TILE, THREADS, SMEM_TOTAL>>>(W, bias, out);
}